// round 1
// baseline (speedup 1.0000x reference)
#include <cuda_runtime.h>
#include <math.h>

#define Bv 8
#define Tv 1024
#define Ev 1024
#define Hv 16
#define Dv 64
#define BH (Bv*Hv)

// Scratch (allocation-free rule: __device__ globals)
__device__ float g_qp[(size_t)BH*Tv*Dv];  // q projected  [bh][t][d]
__device__ float g_vp[(size_t)BH*Tv*Dv];  // v projected  [bh][t][d]
__device__ float g_nw[(size_t)BH*Tv*Dv];  // rnn states   [bh][t][d]
__device__ float g_ao[(size_t)BH*Tv*Dv];  // attn output  [bh][t][d]

// ---------------------------------------------------------------------------
// Generic per-head 64-wide GEMM: C[t, e] = sum_d A[t, d] * W_h[d, e]
// A row at: A + b*sAb + h*sAh + t*sAt (d contiguous)
// C row at: C + b*sCb + h*sCh + t*sCt (e contiguous)
// W_h = W + h*64*64, layout [d][e]
// grid = (Tv/64, BH), block = (16,16)
// ---------------------------------------------------------------------------
__global__ void gemm64_kernel(const float* __restrict__ A,
                              const float* __restrict__ W,
                              float* __restrict__ C,
                              long sAb, long sAh, long sAt,
                              long sCb, long sCh, long sCt)
{
    __shared__ float As[64][65];
    __shared__ float Ws[64][65];

    const int bh = blockIdx.y;
    const int b = bh / Hv, h = bh % Hv;
    const int t0 = blockIdx.x * 64;

    const float* Ab = A + (long)b * sAb + (long)h * sAh;
    const float* Wh = W + (long)h * Dv * Dv;
    float* Cb = C + (long)b * sCb + (long)h * sCh;

    const int tid = threadIdx.y * 16 + threadIdx.x;
    for (int idx = tid; idx < 64 * 64; idx += 256) {
        int r = idx >> 6, c = idx & 63;
        As[r][c] = Ab[(long)(t0 + r) * sAt + c];
        Ws[r][c] = Wh[idx];
    }
    __syncthreads();

    float acc[4][4] = {};
    const int r0 = threadIdx.y * 4, c0 = threadIdx.x * 4;

    #pragma unroll 16
    for (int d = 0; d < 64; d++) {
        float a0 = As[r0 + 0][d], a1 = As[r0 + 1][d];
        float a2 = As[r0 + 2][d], a3 = As[r0 + 3][d];
        float w0 = Ws[d][c0 + 0], w1 = Ws[d][c0 + 1];
        float w2 = Ws[d][c0 + 2], w3 = Ws[d][c0 + 3];
        acc[0][0] += a0 * w0; acc[0][1] += a0 * w1; acc[0][2] += a0 * w2; acc[0][3] += a0 * w3;
        acc[1][0] += a1 * w0; acc[1][1] += a1 * w1; acc[1][2] += a1 * w2; acc[1][3] += a1 * w3;
        acc[2][0] += a2 * w0; acc[2][1] += a2 * w1; acc[2][2] += a2 * w2; acc[2][3] += a2 * w3;
        acc[3][0] += a3 * w0; acc[3][1] += a3 * w1; acc[3][2] += a3 * w2; acc[3][3] += a3 * w3;
    }

    #pragma unroll
    for (int i = 0; i < 4; i++)
        #pragma unroll
        for (int j = 0; j < 4; j++)
            Cb[(long)(t0 + r0 + i) * sCt + (c0 + j)] = acc[i][j];
}

// ---------------------------------------------------------------------------
// RNN: h_{t+1} = tanh((W_ih + W_hh) @ h_t + b_ih + b_hh),
//      h_1 = tanh(W_ih @ k0 + b_ih + b_hh)
// Contraction -> detect exact fp32 fixed point and fill remainder.
// grid = BH blocks, 64 threads (thread e owns output element e).
// ---------------------------------------------------------------------------
__global__ void rnn_kernel(const float* __restrict__ target,
                           const float* __restrict__ Wih,
                           const float* __restrict__ Whh,
                           const float* __restrict__ bih,
                           const float* __restrict__ bhh)
{
    const int bh = blockIdx.x;
    const int b = bh / Hv, h = bh % Hv;
    const int e = threadIdx.x;

    __shared__ float hs[64];
    __shared__ float k0[64];

    k0[e] = target[(long)b * Tv * Ev + (long)h * Dv + e];

    // Row e of W_ih[h] ([e][d] layout per the 'hed' einsum)
    float Mrow[64];
    const float* wi = Wih + ((long)h * Dv + e) * Dv;
    const float* wh = Whh + ((long)h * Dv + e) * Dv;
    #pragma unroll 16
    for (int d = 0; d < 64; d++) Mrow[d] = wi[d];

    const float bias = bih[h * Dv + e] + bhh[h * Dv + e];
    __syncthreads();

    // h1 = tanh(W_ih @ k0 + bias)
    float acc = bias;
    #pragma unroll 16
    for (int d = 0; d < 64; d++) acc += Mrow[d] * k0[d];
    float hcur = tanhf(acc);

    // combined matrix for the recurrence
    #pragma unroll 16
    for (int d = 0; d < 64; d++) Mrow[d] += wh[d];

    float* nwp = g_nw + (long)bh * Tv * Dv;
    hs[e] = hcur;
    nwp[e] = hcur;
    __syncthreads();

    for (int t = 1; t < Tv; t++) {
        float a0 = bias, a1 = 0.f, a2 = 0.f, a3 = 0.f;
        #pragma unroll 8
        for (int d = 0; d < 64; d += 4) {
            a0 += Mrow[d + 0] * hs[d + 0];
            a1 += Mrow[d + 1] * hs[d + 1];
            a2 += Mrow[d + 2] * hs[d + 2];
            a3 += Mrow[d + 3] * hs[d + 3];
        }
        float hn = tanhf((a0 + a1) + (a2 + a3));
        int conv = __syncthreads_and(hn == hcur);  // barrier also covers hs reads
        hs[e] = hn;
        nwp[(long)t * Dv + e] = hn;
        hcur = hn;
        __syncthreads();
        if (conv) {  // exact fixed point: all later states bitwise identical
            for (int t2 = t + 1; t2 < Tv; t2++) nwp[(long)t2 * Dv + e] = hn;
            break;
        }
    }
}

// ---------------------------------------------------------------------------
// Flash attention: per (bh, 64-row q-tile), stream 16 key tiles of 64.
// scores scale = 1/(sqrt(64)*sqrt(1024)) = 1/256 (exact power of 2).
// grid = (16, BH), block = (16,16), dynamic smem = 4*64*65*4 bytes.
// ---------------------------------------------------------------------------
__global__ void attn_kernel()
{
    extern __shared__ float sm[];
    float (*Qs)[65] = (float(*)[65])(sm);
    float (*Ks)[65] = (float(*)[65])(sm + 64 * 65);
    float (*Vs)[65] = (float(*)[65])(sm + 2 * 64 * 65);
    float (*Ps)[65] = (float(*)[65])(sm + 3 * 64 * 65);

    const int bh = blockIdx.y;
    const int q0 = blockIdx.x * 64;
    const float* qp = g_qp + (long)bh * Tv * Dv;
    const float* vp = g_vp + (long)bh * Tv * Dv;
    const float* nwp = g_nw + (long)bh * Tv * Dv;
    float* aop = g_ao + (long)bh * Tv * Dv;

    const int tid = threadIdx.y * 16 + threadIdx.x;
    const int r0 = threadIdx.y * 4, c0 = threadIdx.x * 4;

    for (int idx = tid; idx < 64 * 64; idx += 256) {
        int r = idx >> 6, c = idx & 63;
        Qs[r][c] = qp[(long)(q0 + r) * Dv + c];
    }

    float o[4][4] = {};
    float m[4] = {-1e30f, -1e30f, -1e30f, -1e30f};
    float l[4] = {};
    const float scale = 1.0f / 256.0f;

    for (int kt = 0; kt < Tv / 64; kt++) {
        __syncthreads();  // protects Ks/Vs (prev P@V readers) and Qs first time
        for (int idx = tid; idx < 64 * 64; idx += 256) {
            int r = idx >> 6, c = idx & 63;
            long g = (long)(kt * 64 + r) * Dv + c;
            Ks[r][c] = nwp[g];
            Vs[r][c] = vp[g];
        }
        __syncthreads();

        // S = Q @ K^T (tile), scaled
        float s[4][4] = {};
        #pragma unroll 8
        for (int d = 0; d < 64; d++) {
            float a0 = Qs[r0 + 0][d], a1 = Qs[r0 + 1][d];
            float a2 = Qs[r0 + 2][d], a3 = Qs[r0 + 3][d];
            float k0v = Ks[c0 + 0][d], k1v = Ks[c0 + 1][d];
            float k2v = Ks[c0 + 2][d], k3v = Ks[c0 + 3][d];
            s[0][0] += a0 * k0v; s[0][1] += a0 * k1v; s[0][2] += a0 * k2v; s[0][3] += a0 * k3v;
            s[1][0] += a1 * k0v; s[1][1] += a1 * k1v; s[1][2] += a1 * k2v; s[1][3] += a1 * k3v;
            s[2][0] += a2 * k0v; s[2][1] += a2 * k1v; s[2][2] += a2 * k2v; s[2][3] += a2 * k3v;
            s[3][0] += a3 * k0v; s[3][1] += a3 * k1v; s[3][2] += a3 * k2v; s[3][3] += a3 * k3v;
        }

        // online softmax (row groups = 16 consecutive lanes, reduce via xor shfl)
        #pragma unroll
        for (int i = 0; i < 4; i++) {
            #pragma unroll
            for (int j = 0; j < 4; j++) s[i][j] *= scale;
            float mt = fmaxf(fmaxf(s[i][0], s[i][1]), fmaxf(s[i][2], s[i][3]));
            #pragma unroll
            for (int off = 8; off > 0; off >>= 1)
                mt = fmaxf(mt, __shfl_xor_sync(0xffffffffu, mt, off));
            float mnew = fmaxf(m[i], mt);
            float corr = __expf(m[i] - mnew);
            float ps = 0.f;
            #pragma unroll
            for (int j = 0; j < 4; j++) {
                float p = __expf(s[i][j] - mnew);
                Ps[r0 + i][c0 + j] = p;
                ps += p;
            }
            #pragma unroll
            for (int off = 8; off > 0; off >>= 1)
                ps += __shfl_xor_sync(0xffffffffu, ps, off);
            l[i] = l[i] * corr + ps;
            o[i][0] *= corr; o[i][1] *= corr; o[i][2] *= corr; o[i][3] *= corr;
            m[i] = mnew;
        }
        __syncthreads();

        // O += P @ V
        #pragma unroll 8
        for (int k = 0; k < 64; k++) {
            float p0 = Ps[r0 + 0][k], p1 = Ps[r0 + 1][k];
            float p2 = Ps[r0 + 2][k], p3 = Ps[r0 + 3][k];
            float v0 = Vs[k][c0 + 0], v1 = Vs[k][c0 + 1];
            float v2 = Vs[k][c0 + 2], v3 = Vs[k][c0 + 3];
            o[0][0] += p0 * v0; o[0][1] += p0 * v1; o[0][2] += p0 * v2; o[0][3] += p0 * v3;
            o[1][0] += p1 * v0; o[1][1] += p1 * v1; o[1][2] += p1 * v2; o[1][3] += p1 * v3;
            o[2][0] += p2 * v0; o[2][1] += p2 * v1; o[2][2] += p2 * v2; o[2][3] += p2 * v3;
            o[3][0] += p3 * v0; o[3][1] += p3 * v1; o[3][2] += p3 * v2; o[3][3] += p3 * v3;
        }
    }

    #pragma unroll
    for (int i = 0; i < 4; i++) {
        float inv = 1.0f / l[i];
        #pragma unroll
        for (int j = 0; j < 4; j++)
            aop[(long)(q0 + r0 + i) * Dv + (c0 + j)] = o[i][j] * inv;
    }
}

// ---------------------------------------------------------------------------
extern "C" void kernel_launch(void* const* d_in, const int* in_sizes, int n_in,
                              void* d_out, int out_size)
{
    const float* source = (const float*)d_in[0];
    const float* target = (const float*)d_in[1];
    const float* W_q    = (const float*)d_in[2];
    const float* W_v    = (const float*)d_in[3];
    const float* W_o    = (const float*)d_in[4];
    const float* W_ih   = (const float*)d_in[5];
    const float* W_hh   = (const float*)d_in[6];
    const float* b_ih   = (const float*)d_in[7];
    const float* b_hh   = (const float*)d_in[8];
    float* out = (float*)d_out;

    float *qp, *vp, *ao;
    cudaGetSymbolAddress((void**)&qp, g_qp);
    cudaGetSymbolAddress((void**)&vp, g_vp);
    cudaGetSymbolAddress((void**)&ao, g_ao);

    const int smem_attn = 4 * 64 * 65 * sizeof(float);
    cudaFuncSetAttribute(attn_kernel, cudaFuncAttributeMaxDynamicSharedMemorySize, smem_attn);

    dim3 blk(16, 16);
    dim3 ggrid(Tv / 64, BH);

    // q = source-per-head @ W_q[h]
    gemm64_kernel<<<ggrid, blk>>>(source, W_q, qp,
                                  (long)Tv * Ev, Dv, Ev,
                                  (long)Hv * Tv * Dv, (long)Tv * Dv, Dv);
    // v = target-per-head @ W_v[h]
    gemm64_kernel<<<ggrid, blk>>>(target, W_v, vp,
                                  (long)Tv * Ev, Dv, Ev,
                                  (long)Hv * Tv * Dv, (long)Tv * Dv, Dv);
    // recurrent key states
    rnn_kernel<<<BH, 64>>>(target, W_ih, W_hh, b_ih, b_hh);
    // attention
    attn_kernel<<<dim3(Tv / 64, BH), blk, smem_attn>>>();
    // out = attn_out @ W_o[h], scattered back to [b, t, h*D+e]
    gemm64_kernel<<<ggrid, blk>>>(ao, W_o, out,
                                  (long)Hv * Tv * Dv, (long)Tv * Dv, Dv,
                                  (long)Tv * Ev, Dv, Ev);
}

// round 2
// speedup vs baseline: 1.0000x; 1.0000x over previous
#include <cuda_runtime.h>
#include <math.h>

#define Bv 8
#define Tv 1024
#define Ev 1024
#define Hv 16
#define Dv 64
#define BH (Bv*Hv)

// Scratch (allocation-free rule: __device__ globals)
__device__ float g_qp[(size_t)BH*Tv*Dv];  // q projected  [bh][t][d]
__device__ float g_vp[(size_t)BH*Tv*Dv];  // v projected  [bh][t][d]
__device__ float g_nw[(size_t)BH*Tv*Dv];  // rnn states   [bh][t][d]
__device__ float g_ao[(size_t)BH*Tv*Dv];  // attn output  [bh][t][d]

// ---------------------------------------------------------------------------
// Generic per-head 64-wide GEMM: C[t, e] = sum_d A[t, d] * W_h[d, e]
// A row at: A + b*sAb + h*sAh + t*sAt (d contiguous)
// C row at: C + b*sCb + h*sCh + t*sCt (e contiguous)
// W_h = W + h*64*64, layout [d][e]
// grid = (Tv/64, BH), block = (16,16)
// ---------------------------------------------------------------------------
__global__ void gemm64_kernel(const float* __restrict__ A,
                              const float* __restrict__ W,
                              float* __restrict__ C,
                              long sAb, long sAh, long sAt,
                              long sCb, long sCh, long sCt)
{
    __shared__ float As[64][65];
    __shared__ float Ws[64][65];

    const int bh = blockIdx.y;
    const int b = bh / Hv, h = bh % Hv;
    const int t0 = blockIdx.x * 64;

    const float* Ab = A + (long)b * sAb + (long)h * sAh;
    const float* Wh = W + (long)h * Dv * Dv;
    float* Cb = C + (long)b * sCb + (long)h * sCh;

    const int tid = threadIdx.y * 16 + threadIdx.x;
    for (int idx = tid; idx < 64 * 64; idx += 256) {
        int r = idx >> 6, c = idx & 63;
        As[r][c] = Ab[(long)(t0 + r) * sAt + c];
        Ws[r][c] = Wh[idx];
    }
    __syncthreads();

    float acc[4][4] = {};
    const int r0 = threadIdx.y * 4, c0 = threadIdx.x * 4;

    #pragma unroll 16
    for (int d = 0; d < 64; d++) {
        float a0 = As[r0 + 0][d], a1 = As[r0 + 1][d];
        float a2 = As[r0 + 2][d], a3 = As[r0 + 3][d];
        float w0 = Ws[d][c0 + 0], w1 = Ws[d][c0 + 1];
        float w2 = Ws[d][c0 + 2], w3 = Ws[d][c0 + 3];
        acc[0][0] += a0 * w0; acc[0][1] += a0 * w1; acc[0][2] += a0 * w2; acc[0][3] += a0 * w3;
        acc[1][0] += a1 * w0; acc[1][1] += a1 * w1; acc[1][2] += a1 * w2; acc[1][3] += a1 * w3;
        acc[2][0] += a2 * w0; acc[2][1] += a2 * w1; acc[2][2] += a2 * w2; acc[2][3] += a2 * w3;
        acc[3][0] += a3 * w0; acc[3][1] += a3 * w1; acc[3][2] += a3 * w2; acc[3][3] += a3 * w3;
    }

    #pragma unroll
    for (int i = 0; i < 4; i++)
        #pragma unroll
        for (int j = 0; j < 4; j++)
            Cb[(long)(t0 + r0 + i) * sCt + (c0 + j)] = acc[i][j];
}

// ---------------------------------------------------------------------------
// RNN: h_{t+1} = tanh((W_ih + W_hh) @ h_t + b_ih + b_hh),
//      h_1 = tanh(W_ih @ k0 + b_ih + b_hh)
// Contraction -> detect exact fp32 fixed point and fill remainder.
// grid = BH blocks, 64 threads (thread e owns output element e).
// ---------------------------------------------------------------------------
__global__ void rnn_kernel(const float* __restrict__ target,
                           const float* __restrict__ Wih,
                           const float* __restrict__ Whh,
                           const float* __restrict__ bih,
                           const float* __restrict__ bhh)
{
    const int bh = blockIdx.x;
    const int b = bh / Hv, h = bh % Hv;
    const int e = threadIdx.x;

    __shared__ float hs[64];
    __shared__ float k0[64];

    k0[e] = target[(long)b * Tv * Ev + (long)h * Dv + e];

    // Row e of W_ih[h] ([e][d] layout per the 'hed' einsum)
    float Mrow[64];
    const float* wi = Wih + ((long)h * Dv + e) * Dv;
    const float* wh = Whh + ((long)h * Dv + e) * Dv;
    #pragma unroll 16
    for (int d = 0; d < 64; d++) Mrow[d] = wi[d];

    const float bias = bih[h * Dv + e] + bhh[h * Dv + e];
    __syncthreads();

    // h1 = tanh(W_ih @ k0 + bias)
    float acc = bias;
    #pragma unroll 16
    for (int d = 0; d < 64; d++) acc += Mrow[d] * k0[d];
    float hcur = tanhf(acc);

    // combined matrix for the recurrence
    #pragma unroll 16
    for (int d = 0; d < 64; d++) Mrow[d] += wh[d];

    float* nwp = g_nw + (long)bh * Tv * Dv;
    hs[e] = hcur;
    nwp[e] = hcur;
    __syncthreads();

    for (int t = 1; t < Tv; t++) {
        float a0 = bias, a1 = 0.f, a2 = 0.f, a3 = 0.f;
        #pragma unroll 8
        for (int d = 0; d < 64; d += 4) {
            a0 += Mrow[d + 0] * hs[d + 0];
            a1 += Mrow[d + 1] * hs[d + 1];
            a2 += Mrow[d + 2] * hs[d + 2];
            a3 += Mrow[d + 3] * hs[d + 3];
        }
        float hn = tanhf((a0 + a1) + (a2 + a3));
        int conv = __syncthreads_and(hn == hcur);  // barrier also covers hs reads
        hs[e] = hn;
        nwp[(long)t * Dv + e] = hn;
        hcur = hn;
        __syncthreads();
        if (conv) {  // exact fixed point: all later states bitwise identical
            for (int t2 = t + 1; t2 < Tv; t2++) nwp[(long)t2 * Dv + e] = hn;
            break;
        }
    }
}

// ---------------------------------------------------------------------------
// Flash attention: per (bh, 64-row q-tile), stream 16 key tiles of 64.
// scores scale = 1/(sqrt(64)*sqrt(1024)) = 1/256 (exact power of 2).
// grid = (16, BH), block = (16,16), dynamic smem = 4*64*65*4 bytes.
// ---------------------------------------------------------------------------
__global__ void attn_kernel()
{
    extern __shared__ float sm[];
    float (*Qs)[65] = (float(*)[65])(sm);
    float (*Ks)[65] = (float(*)[65])(sm + 64 * 65);
    float (*Vs)[65] = (float(*)[65])(sm + 2 * 64 * 65);
    float (*Ps)[65] = (float(*)[65])(sm + 3 * 64 * 65);

    const int bh = blockIdx.y;
    const int q0 = blockIdx.x * 64;
    const float* qp = g_qp + (long)bh * Tv * Dv;
    const float* vp = g_vp + (long)bh * Tv * Dv;
    const float* nwp = g_nw + (long)bh * Tv * Dv;
    float* aop = g_ao + (long)bh * Tv * Dv;

    const int tid = threadIdx.y * 16 + threadIdx.x;
    const int r0 = threadIdx.y * 4, c0 = threadIdx.x * 4;

    for (int idx = tid; idx < 64 * 64; idx += 256) {
        int r = idx >> 6, c = idx & 63;
        Qs[r][c] = qp[(long)(q0 + r) * Dv + c];
    }

    float o[4][4] = {};
    float m[4] = {-1e30f, -1e30f, -1e30f, -1e30f};
    float l[4] = {};
    const float scale = 1.0f / 256.0f;

    for (int kt = 0; kt < Tv / 64; kt++) {
        __syncthreads();  // protects Ks/Vs (prev P@V readers) and Qs first time
        for (int idx = tid; idx < 64 * 64; idx += 256) {
            int r = idx >> 6, c = idx & 63;
            long g = (long)(kt * 64 + r) * Dv + c;
            Ks[r][c] = nwp[g];
            Vs[r][c] = vp[g];
        }
        __syncthreads();

        // S = Q @ K^T (tile), scaled
        float s[4][4] = {};
        #pragma unroll 8
        for (int d = 0; d < 64; d++) {
            float a0 = Qs[r0 + 0][d], a1 = Qs[r0 + 1][d];
            float a2 = Qs[r0 + 2][d], a3 = Qs[r0 + 3][d];
            float k0v = Ks[c0 + 0][d], k1v = Ks[c0 + 1][d];
            float k2v = Ks[c0 + 2][d], k3v = Ks[c0 + 3][d];
            s[0][0] += a0 * k0v; s[0][1] += a0 * k1v; s[0][2] += a0 * k2v; s[0][3] += a0 * k3v;
            s[1][0] += a1 * k0v; s[1][1] += a1 * k1v; s[1][2] += a1 * k2v; s[1][3] += a1 * k3v;
            s[2][0] += a2 * k0v; s[2][1] += a2 * k1v; s[2][2] += a2 * k2v; s[2][3] += a2 * k3v;
            s[3][0] += a3 * k0v; s[3][1] += a3 * k1v; s[3][2] += a3 * k2v; s[3][3] += a3 * k3v;
        }

        // online softmax (row groups = 16 consecutive lanes, reduce via xor shfl)
        #pragma unroll
        for (int i = 0; i < 4; i++) {
            #pragma unroll
            for (int j = 0; j < 4; j++) s[i][j] *= scale;
            float mt = fmaxf(fmaxf(s[i][0], s[i][1]), fmaxf(s[i][2], s[i][3]));
            #pragma unroll
            for (int off = 8; off > 0; off >>= 1)
                mt = fmaxf(mt, __shfl_xor_sync(0xffffffffu, mt, off));
            float mnew = fmaxf(m[i], mt);
            float corr = __expf(m[i] - mnew);
            float ps = 0.f;
            #pragma unroll
            for (int j = 0; j < 4; j++) {
                float p = __expf(s[i][j] - mnew);
                Ps[r0 + i][c0 + j] = p;
                ps += p;
            }
            #pragma unroll
            for (int off = 8; off > 0; off >>= 1)
                ps += __shfl_xor_sync(0xffffffffu, ps, off);
            l[i] = l[i] * corr + ps;
            o[i][0] *= corr; o[i][1] *= corr; o[i][2] *= corr; o[i][3] *= corr;
            m[i] = mnew;
        }
        __syncthreads();

        // O += P @ V
        #pragma unroll 8
        for (int k = 0; k < 64; k++) {
            float p0 = Ps[r0 + 0][k], p1 = Ps[r0 + 1][k];
            float p2 = Ps[r0 + 2][k], p3 = Ps[r0 + 3][k];
            float v0 = Vs[k][c0 + 0], v1 = Vs[k][c0 + 1];
            float v2 = Vs[k][c0 + 2], v3 = Vs[k][c0 + 3];
            o[0][0] += p0 * v0; o[0][1] += p0 * v1; o[0][2] += p0 * v2; o[0][3] += p0 * v3;
            o[1][0] += p1 * v0; o[1][1] += p1 * v1; o[1][2] += p1 * v2; o[1][3] += p1 * v3;
            o[2][0] += p2 * v0; o[2][1] += p2 * v1; o[2][2] += p2 * v2; o[2][3] += p2 * v3;
            o[3][0] += p3 * v0; o[3][1] += p3 * v1; o[3][2] += p3 * v2; o[3][3] += p3 * v3;
        }
    }

    #pragma unroll
    for (int i = 0; i < 4; i++) {
        float inv = 1.0f / l[i];
        #pragma unroll
        for (int j = 0; j < 4; j++)
            aop[(long)(q0 + r0 + i) * Dv + (c0 + j)] = o[i][j] * inv;
    }
}

// ---------------------------------------------------------------------------
extern "C" void kernel_launch(void* const* d_in, const int* in_sizes, int n_in,
                              void* d_out, int out_size)
{
    const float* source = (const float*)d_in[0];
    const float* target = (const float*)d_in[1];
    const float* W_q    = (const float*)d_in[2];
    const float* W_v    = (const float*)d_in[3];
    const float* W_o    = (const float*)d_in[4];
    const float* W_ih   = (const float*)d_in[5];
    const float* W_hh   = (const float*)d_in[6];
    const float* b_ih   = (const float*)d_in[7];
    const float* b_hh   = (const float*)d_in[8];
    float* out = (float*)d_out;

    float *qp, *vp, *ao;
    cudaGetSymbolAddress((void**)&qp, g_qp);
    cudaGetSymbolAddress((void**)&vp, g_vp);
    cudaGetSymbolAddress((void**)&ao, g_ao);

    const int smem_attn = 4 * 64 * 65 * sizeof(float);
    cudaFuncSetAttribute(attn_kernel, cudaFuncAttributeMaxDynamicSharedMemorySize, smem_attn);

    dim3 blk(16, 16);
    dim3 ggrid(Tv / 64, BH);

    // q = source-per-head @ W_q[h]
    gemm64_kernel<<<ggrid, blk>>>(source, W_q, qp,
                                  (long)Tv * Ev, Dv, Ev,
                                  (long)Hv * Tv * Dv, (long)Tv * Dv, Dv);
    // v = target-per-head @ W_v[h]
    gemm64_kernel<<<ggrid, blk>>>(target, W_v, vp,
                                  (long)Tv * Ev, Dv, Ev,
                                  (long)Hv * Tv * Dv, (long)Tv * Dv, Dv);
    // recurrent key states
    rnn_kernel<<<BH, 64>>>(target, W_ih, W_hh, b_ih, b_hh);
    // attention
    attn_kernel<<<dim3(Tv / 64, BH), blk, smem_attn>>>();
    // out = attn_out @ W_o[h], scattered back to [b, t, h*D+e]
    gemm64_kernel<<<ggrid, blk>>>(ao, W_o, out,
                                  (long)Hv * Tv * Dv, (long)Tv * Dv, Dv,
                                  (long)Tv * Ev, Dv, Ev);
}

// round 3
// speedup vs baseline: 1.6619x; 1.6619x over previous
#include <cuda_runtime.h>
#include <math.h>

#define Bv 8
#define Tv 1024
#define Ev 1024
#define Hv 16
#define Dv 64
#define BH (Bv*Hv)

#define QT 128   // q rows per block
#define KT 64    // keys per tile
#define PADW 68  // smem row pitch (floats): bank = (4*row + col) % 32, conflict-free

// Scratch (allocation-free rule: __device__ globals)
__device__ float g_qp[(size_t)BH*Tv*Dv];  // q projected  [bh][t][d]
__device__ float g_vp[(size_t)BH*Tv*Dv];  // v projected  [bh][t][d]
__device__ float g_nw[(size_t)BH*Tv*Dv];  // rnn states   [bh][t][d]
__device__ float g_ao[(size_t)BH*Tv*Dv];  // attn output  [bh][t][d]

__device__ __forceinline__ unsigned f2tf32(float f) {
    unsigned u;
    asm("cvt.rna.tf32.f32 %0, %1;" : "=r"(u) : "f"(f));
    return u;
}

__device__ __forceinline__ void mma_tf32(float c[4],
                                         unsigned a0, unsigned a1, unsigned a2, unsigned a3,
                                         unsigned b0, unsigned b1) {
    asm volatile(
        "mma.sync.aligned.m16n8k8.row.col.f32.tf32.tf32.f32 "
        "{%0,%1,%2,%3}, {%4,%5,%6,%7}, {%8,%9}, {%0,%1,%2,%3};"
        : "+f"(c[0]), "+f"(c[1]), "+f"(c[2]), "+f"(c[3])
        : "r"(a0), "r"(a1), "r"(a2), "r"(a3), "r"(b0), "r"(b1));
}

// ---------------------------------------------------------------------------
// Generic per-head 64-wide GEMM (fp32 SIMT): C[t,e] = sum_d A[t,d] * W_h[d,e]
// ---------------------------------------------------------------------------
__global__ void gemm64_kernel(const float* __restrict__ A,
                              const float* __restrict__ W,
                              float* __restrict__ C,
                              long sAb, long sAh, long sAt,
                              long sCb, long sCh, long sCt)
{
    __shared__ float As[64][65];
    __shared__ float Ws[64][65];

    const int bh = blockIdx.y;
    const int b = bh / Hv, h = bh % Hv;
    const int t0 = blockIdx.x * 64;

    const float* Ab = A + (long)b * sAb + (long)h * sAh;
    const float* Wh = W + (long)h * Dv * Dv;
    float* Cb = C + (long)b * sCb + (long)h * sCh;

    const int tid = threadIdx.y * 16 + threadIdx.x;
    for (int idx = tid; idx < 64 * 64; idx += 256) {
        int r = idx >> 6, c = idx & 63;
        As[r][c] = Ab[(long)(t0 + r) * sAt + c];
        Ws[r][c] = Wh[idx];
    }
    __syncthreads();

    float acc[4][4] = {};
    const int r0 = threadIdx.y * 4, c0 = threadIdx.x * 4;

    #pragma unroll 16
    for (int d = 0; d < 64; d++) {
        float a0 = As[r0 + 0][d], a1 = As[r0 + 1][d];
        float a2 = As[r0 + 2][d], a3 = As[r0 + 3][d];
        float w0 = Ws[d][c0 + 0], w1 = Ws[d][c0 + 1];
        float w2 = Ws[d][c0 + 2], w3 = Ws[d][c0 + 3];
        acc[0][0] += a0 * w0; acc[0][1] += a0 * w1; acc[0][2] += a0 * w2; acc[0][3] += a0 * w3;
        acc[1][0] += a1 * w0; acc[1][1] += a1 * w1; acc[1][2] += a1 * w2; acc[1][3] += a1 * w3;
        acc[2][0] += a2 * w0; acc[2][1] += a2 * w1; acc[2][2] += a2 * w2; acc[2][3] += a2 * w3;
        acc[3][0] += a3 * w0; acc[3][1] += a3 * w1; acc[3][2] += a3 * w2; acc[3][3] += a3 * w3;
    }

    #pragma unroll
    for (int i = 0; i < 4; i++)
        #pragma unroll
        for (int j = 0; j < 4; j++)
            Cb[(long)(t0 + r0 + i) * sCt + (c0 + j)] = acc[i][j];
}

// ---------------------------------------------------------------------------
// RNN with exact fp32 fixed-point early exit.
// ---------------------------------------------------------------------------
__global__ void rnn_kernel(const float* __restrict__ target,
                           const float* __restrict__ Wih,
                           const float* __restrict__ Whh,
                           const float* __restrict__ bih,
                           const float* __restrict__ bhh)
{
    const int bh = blockIdx.x;
    const int b = bh / Hv, h = bh % Hv;
    const int e = threadIdx.x;

    __shared__ float hs[64];
    __shared__ float k0[64];

    k0[e] = target[(long)b * Tv * Ev + (long)h * Dv + e];

    float Mrow[64];
    const float* wi = Wih + ((long)h * Dv + e) * Dv;
    const float* wh = Whh + ((long)h * Dv + e) * Dv;
    #pragma unroll 16
    for (int d = 0; d < 64; d++) Mrow[d] = wi[d];

    const float bias = bih[h * Dv + e] + bhh[h * Dv + e];
    __syncthreads();

    float acc = bias;
    #pragma unroll 16
    for (int d = 0; d < 64; d++) acc += Mrow[d] * k0[d];
    float hcur = tanhf(acc);

    #pragma unroll 16
    for (int d = 0; d < 64; d++) Mrow[d] += wh[d];

    float* nwp = g_nw + (long)bh * Tv * Dv;
    hs[e] = hcur;
    nwp[e] = hcur;
    __syncthreads();

    for (int t = 1; t < Tv; t++) {
        float a0 = bias, a1 = 0.f, a2 = 0.f, a3 = 0.f;
        #pragma unroll 8
        for (int d = 0; d < 64; d += 4) {
            a0 += Mrow[d + 0] * hs[d + 0];
            a1 += Mrow[d + 1] * hs[d + 1];
            a2 += Mrow[d + 2] * hs[d + 2];
            a3 += Mrow[d + 3] * hs[d + 3];
        }
        float hn = tanhf((a0 + a1) + (a2 + a3));
        int conv = __syncthreads_and(hn == hcur);
        hs[e] = hn;
        nwp[(long)t * Dv + e] = hn;
        hcur = hn;
        __syncthreads();
        if (conv) {
            for (int t2 = t + 1; t2 < Tv; t2++) nwp[(long)t2 * Dv + e] = hn;
            break;
        }
    }
}

// ---------------------------------------------------------------------------
// Tensor-core flash attention (tf32 mma.sync), no-max softmax (args tiny),
// P = 1 + X split: O = colsum(V) + X @ V  (kills P/V quantization error).
// grid = (Tv/QT, BH), block = 256 (8 warps, 16 q-rows each).
// ---------------------------------------------------------------------------
__global__ void __launch_bounds__(256, 2) attn_tc_kernel()
{
    extern __shared__ unsigned smu[];
    unsigned* Qs = smu;                    // [128][68] tf32
    unsigned* Ks = Qs + QT * PADW;         // [64][68]  tf32 (K = rnn states)
    unsigned* Vs = Ks + KT * PADW;         // [64][68]  tf32
    unsigned* Ps = Vs + KT * PADW;         // [128][68] tf32 (X = p-1)

    const int bh = blockIdx.y;
    const int q0 = blockIdx.x * QT;
    const float* qp  = g_qp + (long)bh * Tv * Dv;
    const float* vp  = g_vp + (long)bh * Tv * Dv;
    const float* nwp = g_nw + (long)bh * Tv * Dv;
    float* aop = g_ao + (long)bh * Tv * Dv;

    const int tid  = threadIdx.x;
    const int warp = tid >> 5, lane = tid & 31;
    const int gid  = lane >> 2, qd = lane & 3;
    const int wrow = warp * 16;

    // stage Q (tf32)
    for (int idx = tid; idx < QT * Dv; idx += 256) {
        int r = idx >> 6, c = idx & 63;
        Qs[r * PADW + c] = f2tf32(qp[(long)(q0 + r) * Dv + c]);
    }

    float o[8][4] = {};          // X @ V accumulators (cols nt*8+2qd, +1; rows gid, gid+8)
    float l0 = 0.f, l1 = 0.f;    // softmax denominators (partial, per quad)
    float rcs = 0.f;             // running colsum(V) partial for col (tid&63)
    const float scale = 1.0f / 256.0f;

    for (int kt = 0; kt < Tv / KT; kt++) {
        __syncthreads();   // Qs ready (first iter) / Ks,Vs free (later iters)
        for (int idx = tid; idx < KT * Dv; idx += 256) {
            int r = idx >> 6, c = idx & 63;
            long g = (long)(kt * KT + r) * Dv + c;
            Ks[r * PADW + c] = f2tf32(nwp[g]);
            float vv = vp[g];
            Vs[r * PADW + c] = f2tf32(vv);
            rcs += vv;         // col (idx&63) == (tid&63), constant per thread
        }
        __syncthreads();

        // S = Q @ K^T
        float s[8][4] = {};
        #pragma unroll
        for (int ks = 0; ks < 8; ks++) {
            unsigned a0 = Qs[(wrow + gid)     * PADW + ks * 8 + qd];
            unsigned a1 = Qs[(wrow + gid + 8) * PADW + ks * 8 + qd];
            unsigned a2 = Qs[(wrow + gid)     * PADW + ks * 8 + qd + 4];
            unsigned a3 = Qs[(wrow + gid + 8) * PADW + ks * 8 + qd + 4];
            #pragma unroll
            for (int nt = 0; nt < 8; nt++) {
                unsigned b0 = Ks[(nt * 8 + gid) * PADW + ks * 8 + qd];
                unsigned b1 = Ks[(nt * 8 + gid) * PADW + ks * 8 + qd + 4];
                mma_tf32(s[nt], a0, a1, a2, a3, b0, b1);
            }
        }

        // p = exp(s/256); store X = p-1 (tf32); accumulate l
        #pragma unroll
        for (int nt = 0; nt < 8; nt++) {
            float p0 = __expf(s[nt][0] * scale);
            float p1 = __expf(s[nt][1] * scale);
            float p2 = __expf(s[nt][2] * scale);
            float p3 = __expf(s[nt][3] * scale);
            l0 += p0 + p1;
            l1 += p2 + p3;
            unsigned* pr0 = Ps + (wrow + gid)     * PADW + nt * 8 + 2 * qd;
            unsigned* pr1 = Ps + (wrow + gid + 8) * PADW + nt * 8 + 2 * qd;
            pr0[0] = f2tf32(p0 - 1.0f); pr0[1] = f2tf32(p1 - 1.0f);
            pr1[0] = f2tf32(p2 - 1.0f); pr1[1] = f2tf32(p3 - 1.0f);
        }
        __syncwarp();   // Ps rows are per-warp private; order writes before reads

        // O += X @ V
        #pragma unroll
        for (int ks = 0; ks < 8; ks++) {
            unsigned a0 = Ps[(wrow + gid)     * PADW + ks * 8 + qd];
            unsigned a1 = Ps[(wrow + gid + 8) * PADW + ks * 8 + qd];
            unsigned a2 = Ps[(wrow + gid)     * PADW + ks * 8 + qd + 4];
            unsigned a3 = Ps[(wrow + gid + 8) * PADW + ks * 8 + qd + 4];
            #pragma unroll
            for (int nt = 0; nt < 8; nt++) {
                unsigned b0 = Vs[(ks * 8 + qd)     * PADW + nt * 8 + gid];
                unsigned b1 = Vs[(ks * 8 + qd + 4) * PADW + nt * 8 + gid];
                mma_tf32(o[nt], a0, a1, a2, a3, b0, b1);
            }
        }
    }

    // total colsum(V): 4 partials per column -> smem (reuse Ks region)
    __syncthreads();
    float* csf = (float*)Ks;
    csf[(tid >> 6) * 64 + (tid & 63)] = rcs;
    __syncthreads();

    // reduce l across the quad (lanes sharing a row)
    l0 += __shfl_xor_sync(0xffffffffu, l0, 1);
    l0 += __shfl_xor_sync(0xffffffffu, l0, 2);
    l1 += __shfl_xor_sync(0xffffffffu, l1, 1);
    l1 += __shfl_xor_sync(0xffffffffu, l1, 2);
    const float inv0 = 1.0f / l0, inv1 = 1.0f / l1;

    const int row0 = q0 + wrow + gid;
    #pragma unroll
    for (int nt = 0; nt < 8; nt++) {
        int col = nt * 8 + 2 * qd;
        float cs0 = csf[col]     + csf[64 + col]     + csf[128 + col]     + csf[192 + col];
        float cs1 = csf[col + 1] + csf[64 + col + 1] + csf[128 + col + 1] + csf[192 + col + 1];
        aop[(long)row0 * Dv + col]           = (o[nt][0] + cs0) * inv0;
        aop[(long)row0 * Dv + col + 1]       = (o[nt][1] + cs1) * inv0;
        aop[(long)(row0 + 8) * Dv + col]     = (o[nt][2] + cs0) * inv1;
        aop[(long)(row0 + 8) * Dv + col + 1] = (o[nt][3] + cs1) * inv1;
    }
}

// ---------------------------------------------------------------------------
extern "C" void kernel_launch(void* const* d_in, const int* in_sizes, int n_in,
                              void* d_out, int out_size)
{
    const float* source = (const float*)d_in[0];
    const float* target = (const float*)d_in[1];
    const float* W_q    = (const float*)d_in[2];
    const float* W_v    = (const float*)d_in[3];
    const float* W_o    = (const float*)d_in[4];
    const float* W_ih   = (const float*)d_in[5];
    const float* W_hh   = (const float*)d_in[6];
    const float* b_ih   = (const float*)d_in[7];
    const float* b_hh   = (const float*)d_in[8];
    float* out = (float*)d_out;

    float *qp, *vp, *ao;
    cudaGetSymbolAddress((void**)&qp, g_qp);
    cudaGetSymbolAddress((void**)&vp, g_vp);
    cudaGetSymbolAddress((void**)&ao, g_ao);

    const int smem_attn = (QT * PADW + 2 * KT * PADW + QT * PADW) * (int)sizeof(unsigned);
    static int configured = 0;
    if (!configured) {
        cudaFuncSetAttribute(attn_tc_kernel, cudaFuncAttributeMaxDynamicSharedMemorySize, smem_attn);
        configured = 1;
    }

    dim3 blk(16, 16);
    dim3 ggrid(Tv / 64, BH);

    gemm64_kernel<<<ggrid, blk>>>(source, W_q, qp,
                                  (long)Tv * Ev, Dv, Ev,
                                  (long)Hv * Tv * Dv, (long)Tv * Dv, Dv);
    gemm64_kernel<<<ggrid, blk>>>(target, W_v, vp,
                                  (long)Tv * Ev, Dv, Ev,
                                  (long)Hv * Tv * Dv, (long)Tv * Dv, Dv);
    rnn_kernel<<<BH, 64>>>(target, W_ih, W_hh, b_ih, b_hh);
    attn_tc_kernel<<<dim3(Tv / QT, BH), 256, smem_attn>>>();
    gemm64_kernel<<<ggrid, blk>>>(ao, W_o, out,
                                  (long)Hv * Tv * Dv, (long)Tv * Dv, Dv,
                                  (long)Tv * Ev, Dv, Ev);
}

// round 4
// speedup vs baseline: 2.1380x; 1.2865x over previous
#include <cuda_runtime.h>
#include <cuda_bf16.h>
#include <math.h>

#define Bv 8
#define Tv 1024
#define Ev 1024
#define Hv 16
#define Dv 64
#define BH (Bv*Hv)

#define QT 128    // q rows per attn CTA
#define KT 64     // keys per tile
#define PK 36     // smem pitch in 32-bit words for bf16-pair tiles (4 mod 32 -> conflict-free frags)

// Scratch (allocation-free rule: __device__ globals)
__device__ float    g_qp [(size_t)BH*Tv*Dv];    // q projected   [bh][t][d] fp32
__device__ float    g_vp [(size_t)BH*Tv*Dv];    // v projected   [bh][t][d] fp32
__device__ float    g_ao [(size_t)BH*Tv*Dv];    // attn output   [bh][t][d] fp32
__device__ unsigned g_nwb[(size_t)BH*Tv*Dv/2];  // rnn states    [bh][t][d/2] bf16x2
__device__ unsigned g_vtb[(size_t)BH*Dv*Tv/2];  // v transposed  [bh][d][t/2] bf16x2
__device__ float    g_cs [(size_t)BH*Dv];       // colsum(V) fp32 [bh][d]

__device__ __forceinline__ unsigned pack2(float lo, float hi) {
    __nv_bfloat162 h = __floats2bfloat162_rn(lo, hi);   // .x = lo (low half)
    return *reinterpret_cast<unsigned*>(&h);
}

__device__ __forceinline__ void mma_bf16(float c[4],
                                         unsigned a0, unsigned a1, unsigned a2, unsigned a3,
                                         unsigned b0, unsigned b1) {
    asm volatile(
        "mma.sync.aligned.m16n8k16.row.col.f32.bf16.bf16.f32 "
        "{%0,%1,%2,%3}, {%4,%5,%6,%7}, {%8,%9}, {%0,%1,%2,%3};"
        : "+f"(c[0]), "+f"(c[1]), "+f"(c[2]), "+f"(c[3])
        : "r"(a0), "r"(a1), "r"(a2), "r"(a3), "r"(b0), "r"(b1));
}

// expm1 for |x| small (here |x| <~ 0.05): 5-term, error < 1e-9, FMA-pipe only
__device__ __forceinline__ float expm1p(float x) {
    float f = fmaf(x, 1.0f/120.0f, 1.0f/24.0f);
    f = fmaf(x, f, 1.0f/6.0f);
    f = fmaf(x, f, 0.5f);
    f = fmaf(x, f, 1.0f);
    return x * f;
}

// ---------------------------------------------------------------------------
// Per-head 64-wide GEMM (fp32, float4-vectorized): C[t,e] = sum_d A[t,d]*W_h[d,e]
// grid = (Tv/64, BH), block = (16,16)
// ---------------------------------------------------------------------------
__global__ void gemm64_kernel(const float* __restrict__ A,
                              const float* __restrict__ W,
                              float* __restrict__ C,
                              long sAb, long sAh, long sAt,
                              long sCb, long sCh, long sCt)
{
    __shared__ float As[64][68];
    __shared__ float Ws[64][68];

    const int bh = blockIdx.y;
    const int b = bh / Hv, h = bh % Hv;
    const int t0 = blockIdx.x * 64;

    const float* Ab = A + (long)b * sAb + (long)h * sAh;
    const float* Wh = W + (long)h * Dv * Dv;
    float* Cb = C + (long)b * sCb + (long)h * sCh;

    const int tid = threadIdx.y * 16 + threadIdx.x;
    for (int idx = tid; idx < 64 * 64; idx += 256) {
        int r = idx >> 6, c = idx & 63;
        As[r][c] = Ab[(long)(t0 + r) * sAt + c];
        Ws[r][c] = Wh[idx];
    }
    __syncthreads();

    float acc[4][4] = {};
    const int r0 = threadIdx.y * 4, c0 = threadIdx.x * 4;

    #pragma unroll
    for (int d = 0; d < 64; d += 4) {
        float4 w0 = *(const float4*)&Ws[d + 0][c0];
        float4 w1 = *(const float4*)&Ws[d + 1][c0];
        float4 w2 = *(const float4*)&Ws[d + 2][c0];
        float4 w3 = *(const float4*)&Ws[d + 3][c0];
        #pragma unroll
        for (int i = 0; i < 4; i++) {
            float4 a = *(const float4*)&As[r0 + i][d];
            acc[i][0] = fmaf(a.x, w0.x, fmaf(a.y, w1.x, fmaf(a.z, w2.x, fmaf(a.w, w3.x, acc[i][0]))));
            acc[i][1] = fmaf(a.x, w0.y, fmaf(a.y, w1.y, fmaf(a.z, w2.y, fmaf(a.w, w3.y, acc[i][1]))));
            acc[i][2] = fmaf(a.x, w0.z, fmaf(a.y, w1.z, fmaf(a.z, w2.z, fmaf(a.w, w3.z, acc[i][2]))));
            acc[i][3] = fmaf(a.x, w0.w, fmaf(a.y, w1.w, fmaf(a.z, w2.w, fmaf(a.w, w3.w, acc[i][3]))));
        }
    }

    #pragma unroll
    for (int i = 0; i < 4; i++)
        #pragma unroll
        for (int j = 0; j < 4; j++)
            Cb[(long)(t0 + r0 + i) * sCt + (c0 + j)] = acc[i][j];
}

// ---------------------------------------------------------------------------
// RNN with exact fp32 fixed-point early exit; emits bf16x2 key states.
// grid = BH, block = 64
// ---------------------------------------------------------------------------
__global__ void rnn_kernel(const float* __restrict__ target,
                           const float* __restrict__ Wih,
                           const float* __restrict__ Whh,
                           const float* __restrict__ bih,
                           const float* __restrict__ bhh)
{
    const int bh = blockIdx.x;
    const int b = bh / Hv, h = bh % Hv;
    const int e = threadIdx.x;

    __shared__ float hs[64];
    __shared__ float k0[64];

    k0[e] = target[(long)b * Tv * Ev + (long)h * Dv + e];

    float Mrow[64];
    const float* wi = Wih + ((long)h * Dv + e) * Dv;
    const float* wh = Whh + ((long)h * Dv + e) * Dv;
    #pragma unroll 16
    for (int d = 0; d < 64; d++) Mrow[d] = wi[d];

    const float bias = bih[h * Dv + e] + bhh[h * Dv + e];
    __syncthreads();

    float acc = bias;
    #pragma unroll 16
    for (int d = 0; d < 64; d++) acc += Mrow[d] * k0[d];
    float hcur = tanhf(acc);

    #pragma unroll 16
    for (int d = 0; d < 64; d++) Mrow[d] += wh[d];

    unsigned* nwb = g_nwb + (long)bh * Tv * (Dv / 2);
    const bool even = (e & 1) == 0;
    const int wofs = e >> 1;

    {
        float hp = __shfl_xor_sync(0xffffffffu, hcur, 1);
        if (even) nwb[wofs] = pack2(hcur, hp);
    }
    hs[e] = hcur;
    __syncthreads();

    for (int t = 1; t < Tv; t++) {
        float a0 = bias, a1 = 0.f, a2 = 0.f, a3 = 0.f;
        #pragma unroll 8
        for (int d = 0; d < 64; d += 4) {
            a0 += Mrow[d + 0] * hs[d + 0];
            a1 += Mrow[d + 1] * hs[d + 1];
            a2 += Mrow[d + 2] * hs[d + 2];
            a3 += Mrow[d + 3] * hs[d + 3];
        }
        float hn = tanhf((a0 + a1) + (a2 + a3));
        int conv = __syncthreads_and(hn == hcur);
        hs[e] = hn;
        float hp = __shfl_xor_sync(0xffffffffu, hn, 1);
        unsigned pk = pack2(hn, hp);
        if (even) nwb[(long)t * (Dv / 2) + wofs] = pk;
        hcur = hn;
        __syncthreads();
        if (conv) {
            if (even)
                for (int t2 = t + 1; t2 < Tv; t2++)
                    nwb[(long)t2 * (Dv / 2) + wofs] = pk;
            break;
        }
    }
}

// ---------------------------------------------------------------------------
// colsum(V) fp32, deterministic. grid = BH, block = 64 (thread d).
// ---------------------------------------------------------------------------
__global__ void colsum_kernel()
{
    const int bh = blockIdx.x, d = threadIdx.x;
    const float* p = g_vp + (long)bh * Tv * Dv + d;
    float s0 = 0.f, s1 = 0.f, s2 = 0.f, s3 = 0.f;
    #pragma unroll 4
    for (int t = 0; t < Tv; t += 4) {
        s0 += p[(t + 0) * Dv];
        s1 += p[(t + 1) * Dv];
        s2 += p[(t + 2) * Dv];
        s3 += p[(t + 3) * Dv];
    }
    g_cs[bh * Dv + d] = (s0 + s1) + (s2 + s3);
}

// ---------------------------------------------------------------------------
// V transpose+convert: fp32 [bh][t][d] -> bf16x2 [bh][d][t/2].
// grid = (Tv/64, BH), block 256.
// ---------------------------------------------------------------------------
__global__ void vtrans_kernel()
{
    __shared__ float sv[64][65];
    const int bh = blockIdx.y;
    const int t0 = blockIdx.x * 64;
    const int tid = threadIdx.x;
    const float* vp = g_vp + (long)bh * Tv * Dv;

    for (int i = tid; i < 64 * 64; i += 256) {
        int t = i >> 6, d = i & 63;
        sv[t][d] = vp[(long)(t0 + t) * Dv + d];
    }
    __syncthreads();

    unsigned* vt = g_vtb + (long)bh * Dv * (Tv / 2);
    for (int i = tid; i < 64 * 32; i += 256) {
        int d = i >> 5, w = i & 31;
        vt[(long)d * (Tv / 2) + (t0 >> 1) + w] = pack2(sv[2 * w][d], sv[2 * w + 1][d]);
    }
}

// ---------------------------------------------------------------------------
// bf16 tensor-core flash attention with register-resident P.
// O = colsum(V) + expm1(S/256) @ V ; l = T + sum expm1.
// grid = (Tv/QT, BH), block 256 (8 warps x 16 q-rows).
// ---------------------------------------------------------------------------
__global__ void __launch_bounds__(256, 2) attn_tc_kernel()
{
    __shared__ unsigned Ks[64 * PK];   // K tile  [key][dword]  bf16x2
    __shared__ unsigned Vt[64 * PK];   // V tile  [d][keyword]  bf16x2

    const int bh = blockIdx.y;
    const int q0 = blockIdx.x * QT;
    const float*    qp  = g_qp  + (long)bh * Tv * Dv;
    const unsigned* nwb = g_nwb + (long)bh * Tv * (Dv / 2);
    const unsigned* vtb = g_vtb + (long)bh * Dv * (Tv / 2);
    float* aop = g_ao + (long)bh * Tv * Dv;

    const int tid  = threadIdx.x;
    const int warp = tid >> 5, lane = tid & 31;
    const int gid  = lane >> 2, qd = lane & 3;
    const int wrow = warp * 16;

    // Q fragments -> registers (bf16 packed), one-time
    unsigned Qa[4][4];
    {
        const int rA = q0 + wrow + gid, rB = rA + 8;
        #pragma unroll
        for (int ks = 0; ks < 4; ks++) {
            int c = ks * 16 + 2 * qd;
            float2 q00 = *(const float2*)(qp + (long)rA * Dv + c);
            float2 q10 = *(const float2*)(qp + (long)rB * Dv + c);
            float2 q01 = *(const float2*)(qp + (long)rA * Dv + c + 8);
            float2 q11 = *(const float2*)(qp + (long)rB * Dv + c + 8);
            Qa[ks][0] = pack2(q00.x, q00.y);
            Qa[ks][1] = pack2(q10.x, q10.y);
            Qa[ks][2] = pack2(q01.x, q01.y);
            Qa[ks][3] = pack2(q11.x, q11.y);
        }
    }

    float o[8][4] = {};
    float lx0 = 0.f, lx1 = 0.f;
    const float scale = 1.0f / 256.0f;

    for (int kt = 0; kt < Tv / KT; kt++) {
        __syncthreads();
        // stage K tile (bf16 copy) and Vt tile
        {
            const unsigned* ksrc = nwb + (long)kt * KT * (Dv / 2);
            const unsigned* vsrc = vtb + (long)kt * (KT / 2);
            #pragma unroll
            for (int i = tid; i < 64 * 32; i += 256) {
                int r = i >> 5, w = i & 31;
                Ks[r * PK + w] = ksrc[r * (Dv / 2) + w];
                Vt[r * PK + w] = vsrc[(long)r * (Tv / 2) + w];
            }
        }
        __syncthreads();

        // S = Q @ K^T
        float s[8][4] = {};
        #pragma unroll
        for (int ks = 0; ks < 4; ks++) {
            #pragma unroll
            for (int nt = 0; nt < 8; nt++) {
                unsigned b0 = Ks[(nt * 8 + gid) * PK + ks * 8 + qd];
                unsigned b1 = Ks[(nt * 8 + gid) * PK + ks * 8 + qd + 4];
                mma_bf16(s[nt], Qa[ks][0], Qa[ks][1], Qa[ks][2], Qa[ks][3], b0, b1);
            }
        }

        // X = expm1(s/256) -> packed A fragments (registers only)
        unsigned Xa[4][4];
        #pragma unroll
        for (int nt = 0; nt < 8; nt++) {
            float x0 = expm1p(s[nt][0] * scale);
            float x1 = expm1p(s[nt][1] * scale);
            float x2 = expm1p(s[nt][2] * scale);
            float x3 = expm1p(s[nt][3] * scale);
            lx0 += x0 + x1;
            lx1 += x2 + x3;
            int kb = nt >> 1, hi = (nt & 1) ? 2 : 0;
            Xa[kb][hi + 0] = pack2(x0, x1);
            Xa[kb][hi + 1] = pack2(x2, x3);
        }

        // O += X @ V
        #pragma unroll
        for (int kb = 0; kb < 4; kb++) {
            #pragma unroll
            for (int nt = 0; nt < 8; nt++) {
                unsigned b0 = Vt[(nt * 8 + gid) * PK + kb * 8 + qd];
                unsigned b1 = Vt[(nt * 8 + gid) * PK + kb * 8 + qd + 4];
                mma_bf16(o[nt], Xa[kb][0], Xa[kb][1], Xa[kb][2], Xa[kb][3], b0, b1);
            }
        }
    }

    // l per row = T + sum X (quad reduce)
    lx0 += __shfl_xor_sync(0xffffffffu, lx0, 1);
    lx0 += __shfl_xor_sync(0xffffffffu, lx0, 2);
    lx1 += __shfl_xor_sync(0xffffffffu, lx1, 1);
    lx1 += __shfl_xor_sync(0xffffffffu, lx1, 2);
    const float inv0 = 1.0f / ((float)Tv + lx0);
    const float inv1 = 1.0f / ((float)Tv + lx1);

    const float* csp = g_cs + bh * Dv;
    const int row0 = q0 + wrow + gid;
    #pragma unroll
    for (int nt = 0; nt < 8; nt++) {
        int col = nt * 8 + 2 * qd;
        float2 cs = *(const float2*)(csp + col);
        aop[(long)row0 * Dv + col]           = (o[nt][0] + cs.x) * inv0;
        aop[(long)row0 * Dv + col + 1]       = (o[nt][1] + cs.y) * inv0;
        aop[(long)(row0 + 8) * Dv + col]     = (o[nt][2] + cs.x) * inv1;
        aop[(long)(row0 + 8) * Dv + col + 1] = (o[nt][3] + cs.y) * inv1;
    }
}

// ---------------------------------------------------------------------------
extern "C" void kernel_launch(void* const* d_in, const int* in_sizes, int n_in,
                              void* d_out, int out_size)
{
    const float* source = (const float*)d_in[0];
    const float* target = (const float*)d_in[1];
    const float* W_q    = (const float*)d_in[2];
    const float* W_v    = (const float*)d_in[3];
    const float* W_o    = (const float*)d_in[4];
    const float* W_ih   = (const float*)d_in[5];
    const float* W_hh   = (const float*)d_in[6];
    const float* b_ih   = (const float*)d_in[7];
    const float* b_hh   = (const float*)d_in[8];
    float* out = (float*)d_out;

    float *qp, *vp, *ao;
    cudaGetSymbolAddress((void**)&qp, g_qp);
    cudaGetSymbolAddress((void**)&vp, g_vp);
    cudaGetSymbolAddress((void**)&ao, g_ao);

    dim3 blk(16, 16);
    dim3 ggrid(Tv / 64, BH);

    gemm64_kernel<<<ggrid, blk>>>(source, W_q, qp,
                                  (long)Tv * Ev, Dv, Ev,
                                  (long)Hv * Tv * Dv, (long)Tv * Dv, Dv);
    gemm64_kernel<<<ggrid, blk>>>(target, W_v, vp,
                                  (long)Tv * Ev, Dv, Ev,
                                  (long)Hv * Tv * Dv, (long)Tv * Dv, Dv);
    rnn_kernel<<<BH, 64>>>(target, W_ih, W_hh, b_ih, b_hh);
    colsum_kernel<<<BH, 64>>>();
    vtrans_kernel<<<dim3(Tv / 64, BH), 256>>>();
    attn_tc_kernel<<<dim3(Tv / QT, BH), 256>>>();
    gemm64_kernel<<<ggrid, blk>>>(ao, W_o, out,
                                  (long)Hv * Tv * Dv, (long)Tv * Dv, Dv,
                                  (long)Tv * Ev, Dv, Ev);
}

// round 5
// speedup vs baseline: 2.4747x; 1.1575x over previous
#include <cuda_runtime.h>
#include <cuda_bf16.h>
#include <math.h>

#define Bv 8
#define Tv 1024
#define Ev 1024
#define Hv 16
#define Dv 64
#define BH (Bv*Hv)

#define QT 128    // q rows per attn CTA
#define KT 64     // keys per tile
#define PK 36     // smem pitch in 32-bit words for bf16-pair tiles (4 mod 32 -> conflict-free frags)
#define PW 36     // smem pitch for packed W tiles

// Scratch (allocation-free rule: __device__ globals)
__device__ unsigned g_qb [(size_t)BH*Tv*Dv/2];  // q projected, packed bf16x2 [bh][t][d/2]
__device__ float    g_vp [(size_t)BH*Tv*Dv];    // v projected   [bh][t][d] fp32
__device__ float    g_ao [(size_t)BH*Tv*Dv];    // attn output   [bh][t][d] fp32
__device__ unsigned g_nwb[(size_t)BH*Tv*Dv/2];  // rnn states    [bh][t][d/2] bf16x2
__device__ unsigned g_vtb[(size_t)BH*Dv*Tv/2];  // v transposed  [bh][d][t/2] bf16x2
__device__ float    g_csp[(size_t)16*BH*Dv];    // partial colsum(V) [kt][bh][d]

__device__ __forceinline__ unsigned pack2(float lo, float hi) {
    __nv_bfloat162 h = __floats2bfloat162_rn(lo, hi);   // .x = lo (low half)
    return *reinterpret_cast<unsigned*>(&h);
}

__device__ __forceinline__ void mma_bf16(float c[4],
                                         unsigned a0, unsigned a1, unsigned a2, unsigned a3,
                                         unsigned b0, unsigned b1) {
    asm volatile(
        "mma.sync.aligned.m16n8k16.row.col.f32.bf16.bf16.f32 "
        "{%0,%1,%2,%3}, {%4,%5,%6,%7}, {%8,%9}, {%0,%1,%2,%3};"
        : "+f"(c[0]), "+f"(c[1]), "+f"(c[2]), "+f"(c[3])
        : "r"(a0), "r"(a1), "r"(a2), "r"(a3), "r"(b0), "r"(b1));
}

// expm1 for |x| small (here |x| <~ 0.05): 5-term, error < 1e-9, FMA-pipe only
__device__ __forceinline__ float expm1p(float x) {
    float f = fmaf(x, 1.0f/120.0f, 1.0f/24.0f);
    f = fmaf(x, f, 1.0f/6.0f);
    f = fmaf(x, f, 0.5f);
    f = fmaf(x, f, 1.0f);
    return x * f;
}

// ---------------------------------------------------------------------------
// Q projection, plain bf16 tensor core. Emits packed bf16x2 fragments-ready
// layout [bh][t][d/2]. grid = (Tv/128, BH), block = 256 (8 warps x 16 rows).
// ---------------------------------------------------------------------------
__global__ void __launch_bounds__(256) proj_q_kernel(const float* __restrict__ A,
                                                     const float* __restrict__ W)
{
    __shared__ unsigned Wt[64 * PW];   // W^T packed: [e][d/2]

    const int bh = blockIdx.y;
    const int b = bh >> 4, h = bh & 15;
    const int tid = threadIdx.x;
    const float* Wh = W + (long)h * Dv * Dv;

    for (int i = tid; i < 64 * 32; i += 256) {
        int e = i >> 5, w = i & 31;
        Wt[e * PW + w] = pack2(Wh[(2 * w) * Dv + e], Wh[(2 * w + 1) * Dv + e]);
    }
    __syncthreads();

    const int warp = tid >> 5, lane = tid & 31;
    const int gid = lane >> 2, qd = lane & 3;
    const int rA = blockIdx.x * 128 + warp * 16 + gid, rB = rA + 8;
    const float* Ab = A + (long)b * Tv * Ev + (long)h * Dv;

    unsigned Qa[4][4];
    #pragma unroll
    for (int ks = 0; ks < 4; ks++) {
        int c = ks * 16 + 2 * qd;
        float2 q00 = *(const float2*)(Ab + (long)rA * Ev + c);
        float2 q10 = *(const float2*)(Ab + (long)rB * Ev + c);
        float2 q01 = *(const float2*)(Ab + (long)rA * Ev + c + 8);
        float2 q11 = *(const float2*)(Ab + (long)rB * Ev + c + 8);
        Qa[ks][0] = pack2(q00.x, q00.y);
        Qa[ks][1] = pack2(q10.x, q10.y);
        Qa[ks][2] = pack2(q01.x, q01.y);
        Qa[ks][3] = pack2(q11.x, q11.y);
    }

    float s[8][4] = {};
    #pragma unroll
    for (int ks = 0; ks < 4; ks++)
        #pragma unroll
        for (int nt = 0; nt < 8; nt++) {
            unsigned b0 = Wt[(nt * 8 + gid) * PW + ks * 8 + qd];
            unsigned b1 = Wt[(nt * 8 + gid) * PW + ks * 8 + qd + 4];
            mma_bf16(s[nt], Qa[ks][0], Qa[ks][1], Qa[ks][2], Qa[ks][3], b0, b1);
        }

    unsigned* ob = g_qb + (long)bh * Tv * 32;
    #pragma unroll
    for (int nt = 0; nt < 8; nt++) {
        ob[(long)rA * 32 + nt * 4 + qd] = pack2(s[nt][0], s[nt][1]);
        ob[(long)rB * 32 + nt * 4 + qd] = pack2(s[nt][2], s[nt][3]);
    }
}

// ---------------------------------------------------------------------------
// Split-bf16 (hi/lo) 3-mma projection, fp32-grade: C = A @ W_h, fp32 out.
// grid = (Tv/128, BH), block = 256.
// ---------------------------------------------------------------------------
__global__ void __launch_bounds__(256) proj_split_kernel(const float* __restrict__ A,
                                                         const float* __restrict__ W,
                                                         float* __restrict__ C,
                                                         long sAb, long sAh, long sAt,
                                                         long sCb, long sCh, long sCt)
{
    __shared__ unsigned Whi[64 * PW];
    __shared__ unsigned Wlo[64 * PW];

    const int bh = blockIdx.y;
    const int b = bh >> 4, h = bh & 15;
    const int tid = threadIdx.x;
    const float* Wh = W + (long)h * Dv * Dv;

    for (int i = tid; i < 64 * 32; i += 256) {
        int e = i >> 5, w = i & 31;
        float w0 = Wh[(2 * w) * Dv + e], w1 = Wh[(2 * w + 1) * Dv + e];
        float h0 = __bfloat162float(__float2bfloat16_rn(w0));
        float h1 = __bfloat162float(__float2bfloat16_rn(w1));
        Whi[e * PW + w] = pack2(h0, h1);
        Wlo[e * PW + w] = pack2(w0 - h0, w1 - h1);
    }
    __syncthreads();

    const int warp = tid >> 5, lane = tid & 31;
    const int gid = lane >> 2, qd = lane & 3;
    const int rA = blockIdx.x * 128 + warp * 16 + gid, rB = rA + 8;
    const float* Ab = A + (long)b * sAb + (long)h * sAh;

    unsigned Ahi[4][4], Alo[4][4];
    #pragma unroll
    for (int ks = 0; ks < 4; ks++) {
        int c = ks * 16 + 2 * qd;
        float2 q00 = *(const float2*)(Ab + (long)rA * sAt + c);
        float2 q10 = *(const float2*)(Ab + (long)rB * sAt + c);
        float2 q01 = *(const float2*)(Ab + (long)rA * sAt + c + 8);
        float2 q11 = *(const float2*)(Ab + (long)rB * sAt + c + 8);
        float h00x = __bfloat162float(__float2bfloat16_rn(q00.x));
        float h00y = __bfloat162float(__float2bfloat16_rn(q00.y));
        float h10x = __bfloat162float(__float2bfloat16_rn(q10.x));
        float h10y = __bfloat162float(__float2bfloat16_rn(q10.y));
        float h01x = __bfloat162float(__float2bfloat16_rn(q01.x));
        float h01y = __bfloat162float(__float2bfloat16_rn(q01.y));
        float h11x = __bfloat162float(__float2bfloat16_rn(q11.x));
        float h11y = __bfloat162float(__float2bfloat16_rn(q11.y));
        Ahi[ks][0] = pack2(h00x, h00y);  Alo[ks][0] = pack2(q00.x - h00x, q00.y - h00y);
        Ahi[ks][1] = pack2(h10x, h10y);  Alo[ks][1] = pack2(q10.x - h10x, q10.y - h10y);
        Ahi[ks][2] = pack2(h01x, h01y);  Alo[ks][2] = pack2(q01.x - h01x, q01.y - h01y);
        Ahi[ks][3] = pack2(h11x, h11y);  Alo[ks][3] = pack2(q11.x - h11x, q11.y - h11y);
    }

    float s[8][4] = {};
    #pragma unroll
    for (int ks = 0; ks < 4; ks++)
        #pragma unroll
        for (int nt = 0; nt < 8; nt++) {
            unsigned b0h = Whi[(nt * 8 + gid) * PW + ks * 8 + qd];
            unsigned b1h = Whi[(nt * 8 + gid) * PW + ks * 8 + qd + 4];
            unsigned b0l = Wlo[(nt * 8 + gid) * PW + ks * 8 + qd];
            unsigned b1l = Wlo[(nt * 8 + gid) * PW + ks * 8 + qd + 4];
            mma_bf16(s[nt], Ahi[ks][0], Ahi[ks][1], Ahi[ks][2], Ahi[ks][3], b0h, b1h);
            mma_bf16(s[nt], Ahi[ks][0], Ahi[ks][1], Ahi[ks][2], Ahi[ks][3], b0l, b1l);
            mma_bf16(s[nt], Alo[ks][0], Alo[ks][1], Alo[ks][2], Alo[ks][3], b0h, b1h);
        }

    float* Cb = C + (long)b * sCb + (long)h * sCh;
    #pragma unroll
    for (int nt = 0; nt < 8; nt++) {
        int col = nt * 8 + 2 * qd;
        *(float2*)(Cb + (long)rA * sCt + col) = make_float2(s[nt][0], s[nt][1]);
        *(float2*)(Cb + (long)rB * sCt + col) = make_float2(s[nt][2], s[nt][3]);
    }
}

// ---------------------------------------------------------------------------
// RNN with exact fp32 fixed-point early exit; emits bf16x2 key states.
// grid = BH, block = 64
// ---------------------------------------------------------------------------
__global__ void rnn_kernel(const float* __restrict__ target,
                           const float* __restrict__ Wih,
                           const float* __restrict__ Whh,
                           const float* __restrict__ bih,
                           const float* __restrict__ bhh)
{
    const int bh = blockIdx.x;
    const int b = bh / Hv, h = bh % Hv;
    const int e = threadIdx.x;

    __shared__ float hs[64];
    __shared__ float k0[64];

    k0[e] = target[(long)b * Tv * Ev + (long)h * Dv + e];

    float Mrow[64];
    const float* wi = Wih + ((long)h * Dv + e) * Dv;
    const float* wh = Whh + ((long)h * Dv + e) * Dv;
    #pragma unroll 16
    for (int d = 0; d < 64; d++) Mrow[d] = wi[d];

    const float bias = bih[h * Dv + e] + bhh[h * Dv + e];
    __syncthreads();

    float acc = bias;
    #pragma unroll 16
    for (int d = 0; d < 64; d++) acc += Mrow[d] * k0[d];
    float hcur = tanhf(acc);

    #pragma unroll 16
    for (int d = 0; d < 64; d++) Mrow[d] += wh[d];

    unsigned* nwb = g_nwb + (long)bh * Tv * (Dv / 2);
    const bool even = (e & 1) == 0;
    const int wofs = e >> 1;

    {
        float hp = __shfl_xor_sync(0xffffffffu, hcur, 1);
        if (even) nwb[wofs] = pack2(hcur, hp);
    }
    hs[e] = hcur;
    __syncthreads();

    for (int t = 1; t < Tv; t++) {
        float a0 = bias, a1 = 0.f, a2 = 0.f, a3 = 0.f;
        #pragma unroll 8
        for (int d = 0; d < 64; d += 4) {
            a0 += Mrow[d + 0] * hs[d + 0];
            a1 += Mrow[d + 1] * hs[d + 1];
            a2 += Mrow[d + 2] * hs[d + 2];
            a3 += Mrow[d + 3] * hs[d + 3];
        }
        float hn = tanhf((a0 + a1) + (a2 + a3));
        int conv = __syncthreads_and(hn == hcur);
        hs[e] = hn;
        float hp = __shfl_xor_sync(0xffffffffu, hn, 1);
        unsigned pk = pack2(hn, hp);
        if (even) nwb[(long)t * (Dv / 2) + wofs] = pk;
        hcur = hn;
        __syncthreads();
        if (conv) {
            if (even)
                for (int t2 = t + 1; t2 < Tv; t2++)
                    nwb[(long)t2 * (Dv / 2) + wofs] = pk;
            break;
        }
    }
}

// ---------------------------------------------------------------------------
// V transpose+convert + per-tile partial colsum (fp32, deterministic order).
// fp32 [bh][t][d] -> bf16x2 [bh][d][t/2]; csp[kt][bh][d] = sum over 64 t's.
// grid = (Tv/64, BH), block 256.
// ---------------------------------------------------------------------------
__global__ void vtrans_kernel()
{
    __shared__ float sv[64][65];
    const int bh = blockIdx.y;
    const int t0 = blockIdx.x * 64;
    const int tid = threadIdx.x;
    const float* vp = g_vp + (long)bh * Tv * Dv;

    for (int i = tid; i < 64 * 64; i += 256) {
        int t = i >> 6, d = i & 63;
        sv[t][d] = vp[(long)(t0 + t) * Dv + d];
    }
    __syncthreads();

    if (tid < 64) {
        float s = 0.f;
        #pragma unroll 16
        for (int t = 0; t < 64; t++) s += sv[t][tid];
        g_csp[((long)blockIdx.x * BH + bh) * Dv + tid] = s;
    }

    unsigned* vt = g_vtb + (long)bh * Dv * (Tv / 2);
    for (int i = tid; i < 64 * 32; i += 256) {
        int d = i >> 5, w = i & 31;
        vt[(long)d * (Tv / 2) + (t0 >> 1) + w] = pack2(sv[2 * w][d], sv[2 * w + 1][d]);
    }
}

// ---------------------------------------------------------------------------
// bf16 tensor-core flash attention with register-resident P.
// O = colsum(V) + expm1(S/256) @ V ; l = T + sum expm1.
// grid = (Tv/QT, BH), block 256 (8 warps x 16 q-rows).
// ---------------------------------------------------------------------------
__global__ void __launch_bounds__(256, 2) attn_tc_kernel()
{
    __shared__ unsigned Ks[64 * PK];   // K tile  [key][dword]  bf16x2
    __shared__ unsigned Vt[64 * PK];   // V tile  [d][keyword]  bf16x2
    __shared__ float csf[64];          // total colsum(V) for this bh

    const int bh = blockIdx.y;
    const int q0 = blockIdx.x * QT;
    const unsigned* qb  = g_qb  + (long)bh * Tv * 32;
    const unsigned* nwb = g_nwb + (long)bh * Tv * (Dv / 2);
    const unsigned* vtb = g_vtb + (long)bh * Dv * (Tv / 2);
    float* aop = g_ao + (long)bh * Tv * Dv;

    const int tid  = threadIdx.x;
    const int warp = tid >> 5, lane = tid & 31;
    const int gid  = lane >> 2, qd = lane & 3;
    const int wrow = warp * 16;

    // total colsum from 16 partials (fixed order -> deterministic)
    if (tid < 64) {
        float s = 0.f;
        #pragma unroll
        for (int p = 0; p < 16; p++) s += g_csp[((long)p * BH + bh) * Dv + tid];
        csf[tid] = s;
    }

    // Q fragments -> registers (already packed bf16x2)
    unsigned Qa[4][4];
    {
        const int rA = q0 + wrow + gid, rB = rA + 8;
        #pragma unroll
        for (int ks = 0; ks < 4; ks++) {
            Qa[ks][0] = qb[(long)rA * 32 + ks * 8 + qd];
            Qa[ks][1] = qb[(long)rB * 32 + ks * 8 + qd];
            Qa[ks][2] = qb[(long)rA * 32 + ks * 8 + qd + 4];
            Qa[ks][3] = qb[(long)rB * 32 + ks * 8 + qd + 4];
        }
    }

    float o[8][4] = {};
    float lx0 = 0.f, lx1 = 0.f;
    const float scale = 1.0f / 256.0f;

    for (int kt = 0; kt < Tv / KT; kt++) {
        __syncthreads();
        // stage K tile and Vt tile
        {
            const unsigned* ksrc = nwb + (long)kt * KT * (Dv / 2);
            const unsigned* vsrc = vtb + (long)kt * (KT / 2);
            #pragma unroll
            for (int i = tid; i < 64 * 32; i += 256) {
                int r = i >> 5, w = i & 31;
                Ks[r * PK + w] = ksrc[r * (Dv / 2) + w];
                Vt[r * PK + w] = vsrc[(long)r * (Tv / 2) + w];
            }
        }
        __syncthreads();

        // S = Q @ K^T
        float s[8][4] = {};
        #pragma unroll
        for (int ks = 0; ks < 4; ks++) {
            #pragma unroll
            for (int nt = 0; nt < 8; nt++) {
                unsigned b0 = Ks[(nt * 8 + gid) * PK + ks * 8 + qd];
                unsigned b1 = Ks[(nt * 8 + gid) * PK + ks * 8 + qd + 4];
                mma_bf16(s[nt], Qa[ks][0], Qa[ks][1], Qa[ks][2], Qa[ks][3], b0, b1);
            }
        }

        // X = expm1(s/256) -> packed A fragments (registers only)
        unsigned Xa[4][4];
        #pragma unroll
        for (int nt = 0; nt < 8; nt++) {
            float x0 = expm1p(s[nt][0] * scale);
            float x1 = expm1p(s[nt][1] * scale);
            float x2 = expm1p(s[nt][2] * scale);
            float x3 = expm1p(s[nt][3] * scale);
            lx0 += x0 + x1;
            lx1 += x2 + x3;
            int kb = nt >> 1, hi = (nt & 1) ? 2 : 0;
            Xa[kb][hi + 0] = pack2(x0, x1);
            Xa[kb][hi + 1] = pack2(x2, x3);
        }

        // O += X @ V
        #pragma unroll
        for (int kb = 0; kb < 4; kb++) {
            #pragma unroll
            for (int nt = 0; nt < 8; nt++) {
                unsigned b0 = Vt[(nt * 8 + gid) * PK + kb * 8 + qd];
                unsigned b1 = Vt[(nt * 8 + gid) * PK + kb * 8 + qd + 4];
                mma_bf16(o[nt], Xa[kb][0], Xa[kb][1], Xa[kb][2], Xa[kb][3], b0, b1);
            }
        }
    }

    // l per row = T + sum X (quad reduce)
    lx0 += __shfl_xor_sync(0xffffffffu, lx0, 1);
    lx0 += __shfl_xor_sync(0xffffffffu, lx0, 2);
    lx1 += __shfl_xor_sync(0xffffffffu, lx1, 1);
    lx1 += __shfl_xor_sync(0xffffffffu, lx1, 2);
    const float inv0 = 1.0f / ((float)Tv + lx0);
    const float inv1 = 1.0f / ((float)Tv + lx1);

    const int row0 = q0 + wrow + gid;
    #pragma unroll
    for (int nt = 0; nt < 8; nt++) {
        int col = nt * 8 + 2 * qd;
        float cs0 = csf[col], cs1 = csf[col + 1];
        aop[(long)row0 * Dv + col]           = (o[nt][0] + cs0) * inv0;
        aop[(long)row0 * Dv + col + 1]       = (o[nt][1] + cs1) * inv0;
        aop[(long)(row0 + 8) * Dv + col]     = (o[nt][2] + cs0) * inv1;
        aop[(long)(row0 + 8) * Dv + col + 1] = (o[nt][3] + cs1) * inv1;
    }
}

// ---------------------------------------------------------------------------
extern "C" void kernel_launch(void* const* d_in, const int* in_sizes, int n_in,
                              void* d_out, int out_size)
{
    const float* source = (const float*)d_in[0];
    const float* target = (const float*)d_in[1];
    const float* W_q    = (const float*)d_in[2];
    const float* W_v    = (const float*)d_in[3];
    const float* W_o    = (const float*)d_in[4];
    const float* W_ih   = (const float*)d_in[5];
    const float* W_hh   = (const float*)d_in[6];
    const float* b_ih   = (const float*)d_in[7];
    const float* b_hh   = (const float*)d_in[8];
    float* out = (float*)d_out;

    float *vp, *ao;
    cudaGetSymbolAddress((void**)&vp, g_vp);
    cudaGetSymbolAddress((void**)&ao, g_ao);

    dim3 pgrid(Tv / 128, BH);

    // q projection -> packed bf16 fragments
    proj_q_kernel<<<pgrid, 256>>>(source, W_q);
    // v projection -> fp32 (split-bf16 3-mma)
    proj_split_kernel<<<pgrid, 256>>>(target, W_v, vp,
                                      (long)Tv * Ev, Dv, Ev,
                                      (long)Hv * Tv * Dv, (long)Tv * Dv, Dv);
    // recurrent key states (bf16 out)
    rnn_kernel<<<BH, 64>>>(target, W_ih, W_hh, b_ih, b_hh);
    // V transpose + partial colsums
    vtrans_kernel<<<dim3(Tv / 64, BH), 256>>>();
    // attention
    attn_tc_kernel<<<dim3(Tv / QT, BH), 256>>>();
    // output projection -> d_out (split-bf16 3-mma)
    proj_split_kernel<<<pgrid, 256>>>(ao, W_o, out,
                                      (long)Hv * Tv * Dv, (long)Tv * Dv, Dv,
                                      (long)Tv * Ev, Dv, Ev);
}